// round 1
// baseline (speedup 1.0000x reference)
#include <cuda_runtime.h>
#include <cuda_bf16.h>

// CARAFE: conv3x3+relu -> conv1x1 -> softmax(100) -> 5x5 reassembly -> pixel_shuffle(2)
// Shapes: x(4,256,64,64) w1(64,256,3,3) b1(64) w2(100,64,1,1) b2(100) -> out(4,256,128,128)

#define B_   4
#define C_   256
#define H_   64
#define W_   64
#define CMID 64
#define NK   100
#define KUP  5

// scratch
__device__ float g_feat[B_ * CMID * H_ * W_];   // 4 MB
__device__ float g_kern[B_ * NK * H_ * W_];     // 6.5 MB

// ---------------------------------------------------------------------------
// Kernel 1: 3x3 conv (pad 1) + bias + ReLU.  x(4,256,64,64) -> feat(4,64,64,64)
// Block: 128 threads, tile 8x8 pixels, all 64 out channels.
// thread: cg = tid>>4 (8 channel-groups of 8), pg = tid&15 -> (py, 4-px strip)
// ---------------------------------------------------------------------------
__global__ __launch_bounds__(128) void conv3x3_relu_kernel(
    const float* __restrict__ x, const float* __restrict__ w1,
    const float* __restrict__ b1)
{
    __shared__ float xs[8][10][12];     // 8 in-ch x 10 rows x (10 cols, pad 12)
    __shared__ float ws[8][64 * 9];     // 8 in-ch x 64 out-ch x 9

    const int tid = threadIdx.x;
    const int cg  = tid >> 4;           // 0..7  -> out channels cg*8..cg*8+7
    const int pg  = tid & 15;           // 0..15
    const int py  = pg >> 1;            // 0..7
    const int px4 = (pg & 1) * 4;       // 0 or 4

    const int x0 = blockIdx.x * 8;
    const int y0 = blockIdx.y * 8;
    const int b  = blockIdx.z;

    float acc[8][4];
#pragma unroll
    for (int m = 0; m < 8; m++)
#pragma unroll
        for (int p = 0; p < 4; p++) acc[m][p] = 0.f;

    for (int c0 = 0; c0 < C_; c0 += 8) {
        __syncthreads();
        // load x tile: 8 x 10 x 10 (zero-pad OOB)
        for (int idx = tid; idx < 800; idx += 128) {
            int cc  = idx / 100;
            int r   = (idx % 100) / 10;
            int col = idx % 10;
            int gy = y0 + r - 1;
            int gx = x0 + col - 1;
            float v = 0.f;
            if (gy >= 0 && gy < H_ && gx >= 0 && gx < W_)
                v = x[((b * C_ + c0 + cc) * H_ + gy) * W_ + gx];
            xs[cc][r][col] = v;
        }
        // load weights: 64 out x 8 in x 9
        for (int idx = tid; idx < 64 * 8 * 9; idx += 128) {
            int m  = idx / 72;
            int r  = idx % 72;
            int cc = r / 9;
            int k  = r % 9;
            ws[cc][m * 9 + k] = w1[(m * C_ + c0 + cc) * 9 + k];
        }
        __syncthreads();

#pragma unroll
        for (int cc = 0; cc < 8; cc++) {
            float xv[3][6];
#pragma unroll
            for (int r = 0; r < 3; r++)
#pragma unroll
                for (int j = 0; j < 6; j++) xv[r][j] = xs[cc][py + r][px4 + j];
#pragma unroll
            for (int m8 = 0; m8 < 8; m8++) {
                const float* wp = &ws[cc][(cg * 8 + m8) * 9];
                float w0 = wp[0], w1v = wp[1], w2v = wp[2];
                float w3 = wp[3], w4v = wp[4], w5v = wp[5];
                float w6 = wp[6], w7v = wp[7], w8v = wp[8];
#pragma unroll
                for (int p = 0; p < 4; p++) {
                    float s = acc[m8][p];
                    s += w0 * xv[0][p]     + w1v * xv[0][p + 1] + w2v * xv[0][p + 2];
                    s += w3 * xv[1][p]     + w4v * xv[1][p + 1] + w5v * xv[1][p + 2];
                    s += w6 * xv[2][p]     + w7v * xv[2][p + 1] + w8v * xv[2][p + 2];
                    acc[m8][p] = s;
                }
            }
        }
    }

#pragma unroll
    for (int m8 = 0; m8 < 8; m8++) {
        int m = cg * 8 + m8;
        float bias = b1[m];
#pragma unroll
        for (int p = 0; p < 4; p++) {
            float v = acc[m8][p] + bias;
            v = v > 0.f ? v : 0.f;
            g_feat[((b * CMID + m) * H_ + y0 + py) * W_ + x0 + px4 + p] = v;
        }
    }
}

// ---------------------------------------------------------------------------
// Kernel 2: 1x1 conv (64 -> 100) + bias + softmax over 100 channels.
// Block: 256 threads = 4 j-groups (25 outputs each) x 64 pixels.
// ---------------------------------------------------------------------------
__global__ __launch_bounds__(256) void conv1x1_softmax_kernel(
    const float* __restrict__ w2, const float* __restrict__ b2)
{
    __shared__ float fs[64][64];        // [k][pixel]
    __shared__ float w2s[NK][64];       // [j][k]
    __shared__ float redm[4][64];
    __shared__ float reds[4][64];

    const int tid = threadIdx.x;
    const int jg  = tid >> 6;           // 0..3
    const int pix = tid & 63;

    const int b  = blockIdx.x >> 6;
    const int p0 = (blockIdx.x & 63) * 64;

    for (int idx = tid; idx < 64 * 64; idx += 256) {
        int k = idx >> 6, i = idx & 63;
        fs[k][i] = g_feat[(b * CMID + k) * (H_ * W_) + p0 + i];
    }
    for (int idx = tid; idx < NK * 64; idx += 256) {
        int j = idx >> 6, k = idx & 63;
        w2s[j][k] = w2[j * 64 + k];
    }
    __syncthreads();

    float acc[25];
#pragma unroll
    for (int jj = 0; jj < 25; jj++) acc[jj] = b2[jg * 25 + jj];

    for (int k = 0; k < 64; k++) {
        float f = fs[k][pix];
#pragma unroll
        for (int jj = 0; jj < 25; jj++)
            acc[jj] += f * w2s[jg * 25 + jj][k];
    }

    // softmax over full 100 channels
    float lmax = acc[0];
#pragma unroll
    for (int jj = 1; jj < 25; jj++) lmax = fmaxf(lmax, acc[jj]);
    redm[jg][pix] = lmax;
    __syncthreads();
    float gmax = fmaxf(fmaxf(redm[0][pix], redm[1][pix]),
                       fmaxf(redm[2][pix], redm[3][pix]));
    float lsum = 0.f;
#pragma unroll
    for (int jj = 0; jj < 25; jj++) {
        acc[jj] = __expf(acc[jj] - gmax);
        lsum += acc[jj];
    }
    reds[jg][pix] = lsum;
    __syncthreads();
    float gsum = reds[0][pix] + reds[1][pix] + reds[2][pix] + reds[3][pix];
    float inv = 1.f / gsum;
#pragma unroll
    for (int jj = 0; jj < 25; jj++)
        g_kern[(b * NK + jg * 25 + jj) * (H_ * W_) + p0 + pix] = acc[jj] * inv;
}

// ---------------------------------------------------------------------------
// Kernel 3: reassembly + pixel shuffle.
// out[b][s*64 + (c>>2)][2h + ((c>>1)&1)][2w + (c&1)] =
//      sum_k kern[b][s*25+k][h][w] * xpad[b][c][h+kh-2][w+kw-2]
// Block: 128 threads = 2 s-groups (2 s each) x 64 pixels (8x8 tile).
// ---------------------------------------------------------------------------
__global__ __launch_bounds__(128) void reassembly_kernel(
    const float* __restrict__ x, float* __restrict__ out)
{
    __shared__ float xs[32][12][12];    // 32 ch x 12x12 spatial (pad 2 halo)

    const int tid = threadIdx.x;
    const int sg  = tid >> 6;           // 0..1 -> s in {2sg, 2sg+1}
    const int pix = tid & 63;
    const int py  = pix >> 3;
    const int px  = pix & 7;

    const int x0 = blockIdx.x * 8;
    const int y0 = blockIdx.y * 8;
    const int b  = blockIdx.z;
    const int gy = y0 + py, gx = x0 + px;

    // register-cache the 2x25 softmaxed kernel weights for this pixel
    float kreg[2][25];
#pragma unroll
    for (int s2 = 0; s2 < 2; s2++) {
        int s = sg * 2 + s2;
#pragma unroll
        for (int k = 0; k < 25; k++)
            kreg[s2][k] = g_kern[((b * NK + s * 25 + k) * H_ + gy) * W_ + gx];
    }

    for (int c0 = 0; c0 < C_; c0 += 32) {
        __syncthreads();
        // load 32 x 12 x 12 x-tile with halo 2 (zero-pad)
        for (int idx = tid; idx < 32 * 144; idx += 128) {
            int cc  = idx / 144;
            int r   = (idx % 144) / 12;
            int col = idx % 12;
            int yy = y0 + r - 2;
            int xx = x0 + col - 2;
            float v = 0.f;
            if (yy >= 0 && yy < H_ && xx >= 0 && xx < W_)
                v = x[((b * C_ + c0 + cc) * H_ + yy) * W_ + xx];
            xs[cc][r][col] = v;
        }
        __syncthreads();

#pragma unroll 2
        for (int cc = 0; cc < 32; cc += 2) {
            float a00 = 0.f, a10 = 0.f;   // s2=0/1, channel cc
            float a01 = 0.f, a11 = 0.f;   // s2=0/1, channel cc+1
#pragma unroll
            for (int kh = 0; kh < 5; kh++)
#pragma unroll
                for (int kw = 0; kw < 5; kw++) {
                    int k = kh * 5 + kw;
                    float v0 = xs[cc][py + kh][px + kw];
                    float v1 = xs[cc + 1][py + kh][px + kw];
                    a00 += kreg[0][k] * v0;
                    a10 += kreg[1][k] * v0;
                    a01 += kreg[0][k] * v1;
                    a11 += kreg[1][k] * v1;
                }
            int c = c0 + cc;              // even -> (c, c+1) share q and row bit
            int q4 = c >> 2;              // c/4
            int a  = (c >> 1) & 1;        // row sub-index
            int oy = 2 * gy + a;
            int ox = 2 * gx;
#pragma unroll
            for (int s2 = 0; s2 < 2; s2++) {
                int s = sg * 2 + s2;
                int q = s * 64 + q4;
                float2 v;
                v.x = (s2 == 0) ? a00 : a10;
                v.y = (s2 == 0) ? a01 : a11;
                *reinterpret_cast<float2*>(
                    &out[((size_t)(b * C_ + q) * 128 + oy) * 128 + ox]) = v;
            }
        }
    }
}

// ---------------------------------------------------------------------------
extern "C" void kernel_launch(void* const* d_in, const int* in_sizes, int n_in,
                              void* d_out, int out_size)
{
    const float* x  = (const float*)d_in[0];
    const float* w1 = (const float*)d_in[1];
    const float* b1 = (const float*)d_in[2];
    const float* w2 = (const float*)d_in[3];
    const float* b2 = (const float*)d_in[4];
    float* out = (float*)d_out;

    dim3 gtile(W_ / 8, H_ / 8, B_);
    conv3x3_relu_kernel<<<gtile, 128>>>(x, w1, b1);
    conv1x1_softmax_kernel<<<B_ * (H_ * W_) / 64, 256>>>(w2, b2);
    reassembly_kernel<<<gtile, 128>>>(x, out);
}

// round 2
// speedup vs baseline: 1.4063x; 1.4063x over previous
#include <cuda_runtime.h>
#include <cuda_bf16.h>

// CARAFE: conv3x3+relu -> conv1x1 -> softmax(100) -> 5x5 reassembly -> pixel_shuffle(2)
// Shapes: x(4,256,64,64) w1(64,256,3,3) b1(64) w2(100,64,1,1) b2(100) -> out(4,256,128,128)

#define B_   4
#define C_   256
#define H_   64
#define W_   64
#define CMID 64
#define NK   100
#define KUP  5
#define NSPLIT 4          // input-channel splits for occupancy
#define CSPL (C_ / NSPLIT)

// scratch
__device__ float g_feat_part[NSPLIT * B_ * CMID * H_ * W_];  // 16 MB partial sums
__device__ float g_kern[B_ * NK * H_ * W_];                  // 6.5 MB

// ---------------------------------------------------------------------------
// Kernel 1: 3x3 conv (pad 1) PARTIAL over 64 input channels.
// grid = (8, 8, B*NSPLIT); block = 128.
// Each CTA: 8x8 pixel tile, all 64 out channels, input channels [split*64, +64).
// ---------------------------------------------------------------------------
__global__ __launch_bounds__(128) void conv3x3_part_kernel(
    const float* __restrict__ x, const float* __restrict__ w1)
{
    __shared__ float xs[8][10][12];     // 8 in-ch x 10 rows x (10 cols, pad 12)
    __shared__ float ws[8][64 * 9];     // 8 in-ch x 64 out-ch x 9

    const int tid = threadIdx.x;
    const int cg  = tid >> 4;           // 0..7  -> out channels cg*8..cg*8+7
    const int pg  = tid & 15;           // 0..15
    const int py  = pg >> 1;            // 0..7
    const int px4 = (pg & 1) * 4;       // 0 or 4

    const int x0 = blockIdx.x * 8;
    const int y0 = blockIdx.y * 8;
    const int b  = blockIdx.z >> 2;
    const int sp = blockIdx.z & 3;
    const int cbase = sp * CSPL;

    float acc[8][4];
#pragma unroll
    for (int m = 0; m < 8; m++)
#pragma unroll
        for (int p = 0; p < 4; p++) acc[m][p] = 0.f;

    for (int c0 = cbase; c0 < cbase + CSPL; c0 += 8) {
        __syncthreads();
        // load x tile: 8 x 10 x 10 (zero-pad OOB)
        for (int idx = tid; idx < 800; idx += 128) {
            int cc  = idx / 100;
            int r   = (idx % 100) / 10;
            int col = idx % 10;
            int gy = y0 + r - 1;
            int gx = x0 + col - 1;
            float v = 0.f;
            if (gy >= 0 && gy < H_ && gx >= 0 && gx < W_)
                v = x[((b * C_ + c0 + cc) * H_ + gy) * W_ + gx];
            xs[cc][r][col] = v;
        }
        // load weights: 64 out x 8 in x 9
        for (int idx = tid; idx < 64 * 8 * 9; idx += 128) {
            int m  = idx / 72;
            int r  = idx % 72;
            int cc = r / 9;
            int k  = r % 9;
            ws[cc][m * 9 + k] = w1[(m * C_ + c0 + cc) * 9 + k];
        }
        __syncthreads();

#pragma unroll
        for (int cc = 0; cc < 8; cc++) {
            float xv[3][6];
#pragma unroll
            for (int r = 0; r < 3; r++)
#pragma unroll
                for (int j = 0; j < 6; j++) xv[r][j] = xs[cc][py + r][px4 + j];
#pragma unroll
            for (int m8 = 0; m8 < 8; m8++) {
                const float* wp = &ws[cc][(cg * 8 + m8) * 9];
                float w0 = wp[0], w1v = wp[1], w2v = wp[2];
                float w3 = wp[3], w4v = wp[4], w5v = wp[5];
                float w6 = wp[6], w7v = wp[7], w8v = wp[8];
#pragma unroll
                for (int p = 0; p < 4; p++) {
                    float s = acc[m8][p];
                    s += w0 * xv[0][p]     + w1v * xv[0][p + 1] + w2v * xv[0][p + 2];
                    s += w3 * xv[1][p]     + w4v * xv[1][p + 1] + w5v * xv[1][p + 2];
                    s += w6 * xv[2][p]     + w7v * xv[2][p + 1] + w8v * xv[2][p + 2];
                    acc[m8][p] = s;
                }
            }
        }
    }

#pragma unroll
    for (int m8 = 0; m8 < 8; m8++) {
        int m = cg * 8 + m8;
#pragma unroll
        for (int p = 0; p < 4; p++) {
            g_feat_part[(((sp * B_ + b) * CMID + m) * H_ + y0 + py) * W_ + x0 + px4 + p]
                = acc[m8][p];
        }
    }
}

// ---------------------------------------------------------------------------
// Kernel 2: combine partials + bias + ReLU, then 1x1 conv (64->100) + softmax.
// Block: 256 threads = 4 j-groups (25 outputs each) x 64 pixels.
// ---------------------------------------------------------------------------
__global__ __launch_bounds__(256) void conv1x1_softmax_kernel(
    const float* __restrict__ b1,
    const float* __restrict__ w2, const float* __restrict__ b2)
{
    __shared__ float fs[64][64];        // [k][pixel]
    __shared__ float w2s[NK][64];       // [j][k]
    __shared__ float redm[4][64];
    __shared__ float reds[4][64];

    const int tid = threadIdx.x;
    const int jg  = tid >> 6;           // 0..3
    const int pix = tid & 63;

    const int b  = blockIdx.x >> 6;
    const int p0 = (blockIdx.x & 63) * 64;

    for (int idx = tid; idx < 64 * 64; idx += 256) {
        int k = idx >> 6, i = idx & 63;
        float v = b1[k];
#pragma unroll
        for (int p = 0; p < NSPLIT; p++)
            v += g_feat_part[((p * B_ + b) * CMID + k) * (H_ * W_) + p0 + i];
        fs[k][i] = v > 0.f ? v : 0.f;
    }
    for (int idx = tid; idx < NK * 64; idx += 256) {
        int j = idx >> 6, k = idx & 63;
        w2s[j][k] = w2[j * 64 + k];
    }
    __syncthreads();

    float acc[25];
#pragma unroll
    for (int jj = 0; jj < 25; jj++) acc[jj] = b2[jg * 25 + jj];

    for (int k = 0; k < 64; k++) {
        float f = fs[k][pix];
#pragma unroll
        for (int jj = 0; jj < 25; jj++)
            acc[jj] += f * w2s[jg * 25 + jj][k];
    }

    // softmax over full 100 channels
    float lmax = acc[0];
#pragma unroll
    for (int jj = 1; jj < 25; jj++) lmax = fmaxf(lmax, acc[jj]);
    redm[jg][pix] = lmax;
    __syncthreads();
    float gmax = fmaxf(fmaxf(redm[0][pix], redm[1][pix]),
                       fmaxf(redm[2][pix], redm[3][pix]));
    float lsum = 0.f;
#pragma unroll
    for (int jj = 0; jj < 25; jj++) {
        acc[jj] = __expf(acc[jj] - gmax);
        lsum += acc[jj];
    }
    reds[jg][pix] = lsum;
    __syncthreads();
    float gsum = reds[0][pix] + reds[1][pix] + reds[2][pix] + reds[3][pix];
    float inv = 1.f / gsum;
#pragma unroll
    for (int jj = 0; jj < 25; jj++)
        g_kern[(b * NK + jg * 25 + jj) * (H_ * W_) + p0 + pix] = acc[jj] * inv;
}

// ---------------------------------------------------------------------------
// Kernel 3: reassembly + pixel shuffle, channel-split over grid for occupancy.
// out[b][s*64 + (c>>2)][2h + ((c>>1)&1)][2w + (c&1)] =
//      sum_k kern[b][s*25+k][h][w] * xpad[b][c][h+kh-2][w+kw-2]
// grid = (8, 8, B*NSPLIT); block: 128 threads = 2 s-groups x 64 pixels.
// ---------------------------------------------------------------------------
__global__ __launch_bounds__(128) void reassembly_kernel(
    const float* __restrict__ x, float* __restrict__ out)
{
    __shared__ float xs[32][12][12];    // 32 ch x 12x12 spatial (pad 2 halo)

    const int tid = threadIdx.x;
    const int sg  = tid >> 6;           // 0..1 -> s in {2sg, 2sg+1}
    const int pix = tid & 63;
    const int py  = pix >> 3;
    const int px  = pix & 7;

    const int x0 = blockIdx.x * 8;
    const int y0 = blockIdx.y * 8;
    const int b  = blockIdx.z >> 2;
    const int sp = blockIdx.z & 3;
    const int gy = y0 + py, gx = x0 + px;

    // register-cache the 2x25 softmaxed kernel weights for this pixel
    float kreg[2][25];
#pragma unroll
    for (int s2 = 0; s2 < 2; s2++) {
        int s = sg * 2 + s2;
#pragma unroll
        for (int k = 0; k < 25; k++)
            kreg[s2][k] = g_kern[((b * NK + s * 25 + k) * H_ + gy) * W_ + gx];
    }

    for (int c0 = sp * CSPL; c0 < sp * CSPL + CSPL; c0 += 32) {
        __syncthreads();
        // load 32 x 12 x 12 x-tile with halo 2 (zero-pad)
        for (int idx = tid; idx < 32 * 144; idx += 128) {
            int cc  = idx / 144;
            int r   = (idx % 144) / 12;
            int col = idx % 12;
            int yy = y0 + r - 2;
            int xx = x0 + col - 2;
            float v = 0.f;
            if (yy >= 0 && yy < H_ && xx >= 0 && xx < W_)
                v = x[((b * C_ + c0 + cc) * H_ + yy) * W_ + xx];
            xs[cc][r][col] = v;
        }
        __syncthreads();

#pragma unroll 2
        for (int cc = 0; cc < 32; cc += 2) {
            float a00 = 0.f, a10 = 0.f;   // s2=0/1, channel cc
            float a01 = 0.f, a11 = 0.f;   // s2=0/1, channel cc+1
#pragma unroll
            for (int kh = 0; kh < 5; kh++)
#pragma unroll
                for (int kw = 0; kw < 5; kw++) {
                    int k = kh * 5 + kw;
                    float v0 = xs[cc][py + kh][px + kw];
                    float v1 = xs[cc + 1][py + kh][px + kw];
                    a00 += kreg[0][k] * v0;
                    a10 += kreg[1][k] * v0;
                    a01 += kreg[0][k] * v1;
                    a11 += kreg[1][k] * v1;
                }
            int c = c0 + cc;              // even -> (c, c+1) share q and row bit
            int q4 = c >> 2;              // c/4
            int a  = (c >> 1) & 1;        // row sub-index
            int oy = 2 * gy + a;
            int ox = 2 * gx;
#pragma unroll
            for (int s2 = 0; s2 < 2; s2++) {
                int s = sg * 2 + s2;
                int q = s * 64 + q4;
                float2 v;
                v.x = (s2 == 0) ? a00 : a10;
                v.y = (s2 == 0) ? a01 : a11;
                *reinterpret_cast<float2*>(
                    &out[((size_t)(b * C_ + q) * 128 + oy) * 128 + ox]) = v;
            }
        }
    }
}

// ---------------------------------------------------------------------------
extern "C" void kernel_launch(void* const* d_in, const int* in_sizes, int n_in,
                              void* d_out, int out_size)
{
    const float* x  = (const float*)d_in[0];
    const float* w1 = (const float*)d_in[1];
    const float* b1 = (const float*)d_in[2];
    const float* w2 = (const float*)d_in[3];
    const float* b2 = (const float*)d_in[4];
    float* out = (float*)d_out;

    dim3 gsplit(W_ / 8, H_ / 8, B_ * NSPLIT);
    conv3x3_part_kernel<<<gsplit, 128>>>(x, w1);
    conv1x1_softmax_kernel<<<B_ * (H_ * W_) / 64, 256>>>(b1, w2, b2);
    reassembly_kernel<<<gsplit, 128>>>(x, out);
}

// round 4
// speedup vs baseline: 2.1290x; 1.5139x over previous
#include <cuda_runtime.h>
#include <cuda_fp16.h>
#include <cstdint>

// CARAFE: conv3x3(+bias+relu) via fp16 split-precision mma.sync implicit GEMM,
// then conv1x1+softmax, then 5x5 reassembly + pixel_shuffle(2).
// x(4,256,64,64) w1(64,256,3,3) b1(64) w2(100,64) b2(100) -> out(4,256,128,128)

#define B_   4
#define C_   256
#define H_   64
#define W_   64
#define CMID 64
#define NK   100
#define NSPLIT 4
#define CSPL (C_ / NSPLIT)

#define KTOT   (C_ * 9)     // 2304
#define KC     64           // k per staged chunk
#define NCHUNK (KTOT / KC)  // 36

#define NX (B_ * C_ * H_ * W_)   // 4194304
#define NW (CMID * KTOT)         // 147456

// scratch
__device__ float  g_feat[B_ * CMID * H_ * W_];
__device__ float  g_kern[B_ * NK * H_ * W_];
__device__ __half g_xh[NX];
__device__ __half g_xl[NX];     // 2048*(x - hi)
__device__ __half g_wh[NW];
__device__ __half g_wl[NW];     // 2048*(w - hi)

__device__ __forceinline__ uint32_t s2u(const void* p) {
    uint32_t a;
    asm("{ .reg .u64 t; cvta.to.shared.u64 t, %1; cvt.u32.u64 %0, t; }"
        : "=r"(a) : "l"(p));
    return a;
}
__device__ __forceinline__ void ldsm4(uint32_t* r, uint32_t addr) {
    asm volatile("ldmatrix.sync.aligned.m8n8.x4.shared.b16 {%0,%1,%2,%3}, [%4];"
                 : "=r"(r[0]), "=r"(r[1]), "=r"(r[2]), "=r"(r[3]) : "r"(addr));
}
__device__ __forceinline__ void ldsm4t(uint32_t* r, uint32_t addr) {
    asm volatile("ldmatrix.sync.aligned.m8n8.x4.trans.shared.b16 {%0,%1,%2,%3}, [%4];"
                 : "=r"(r[0]), "=r"(r[1]), "=r"(r[2]), "=r"(r[3]) : "r"(addr));
}
__device__ __forceinline__ void mma16816(float* d, const uint32_t* a,
                                         uint32_t b0, uint32_t b1) {
    asm volatile(
        "mma.sync.aligned.m16n8k16.row.col.f32.f16.f16.f32 "
        "{%0,%1,%2,%3}, {%4,%5,%6,%7}, {%8,%9}, {%0,%1,%2,%3};"
        : "+f"(d[0]), "+f"(d[1]), "+f"(d[2]), "+f"(d[3])
        : "r"(a[0]), "r"(a[1]), "r"(a[2]), "r"(a[3]), "r"(b0), "r"(b1));
}
__device__ __forceinline__ uint32_t pack2(__half a, __half b) {
    return (uint32_t)__half_as_ushort(a) | ((uint32_t)__half_as_ushort(b) << 16);
}

// ---------------------------------------------------------------------------
// Kernel 0: fp16 hi/lo conversion of x and w1 (lo scaled by 2048).
// ---------------------------------------------------------------------------
__global__ void convert_kernel(const float* __restrict__ x,
                               const float* __restrict__ w1)
{
    for (int i = blockIdx.x * blockDim.x + threadIdx.x; i < NX;
         i += gridDim.x * blockDim.x) {
        float v = x[i];
        __half h = __float2half_rn(v);
        g_xh[i] = h;
        g_xl[i] = __float2half_rn((v - __half2float(h)) * 2048.f);
        if (i < NW) {
            float w = w1[i];
            __half wh = __float2half_rn(w);
            g_wh[i] = wh;
            g_wl[i] = __float2half_rn((w - __half2float(wh)) * 2048.f);
        }
    }
}

// ---------------------------------------------------------------------------
// Kernel 1: conv3x3 + bias + ReLU as fp16 HMMA implicit GEMM.
// grid = 256 (b,h = one image row, M=64 pixels); block = 256 (8 warps).
// warp (wid&3) -> m0 = 16*(wid&3); (wid>>2) -> n0 = 32*(wid>>2).
// 3-pass split: D = Ah*Bh + (Ah*Bl' + Al'*Bh)/2048.
// ---------------------------------------------------------------------------
__global__ __launch_bounds__(256, 2) void conv3x3_hmma_kernel(
    const float* __restrict__ b1)
{
    __shared__ __half ATh[KC][72];      // [k][pixel], 144B rows (ldmatrix-friendly)
    __shared__ __half ATl[KC][72];
    __shared__ __half Bsh[CMID][72];    // [n][k]
    __shared__ __half Bsl[CMID][72];
    __shared__ __half rawh[8][3][68];   // padded raw rows: col t = x px (t-1)
    __shared__ __half rawl[8][3][68];

    const int tid  = threadIdx.x;
    const int lane = tid & 31;
    const int wid  = tid >> 5;
    const int b    = blockIdx.x >> 6;
    const int h    = blockIdx.x & 63;

    const int m0 = (wid & 3) * 16;
    const int n0 = (wid >> 2) * 32;

    // ldmatrix lane addressing (shared by A-trans and B):
    const int lrow  = (lane & 7) + ((lane >> 4) & 1) * 8;
    const int lcol8 = ((lane >> 3) & 1) * 8;

    const uint32_t sATh = s2u(ATh), sATl = s2u(ATl);
    const uint32_t sBh  = s2u(Bsh), sBl  = s2u(Bsl);

    float accM[4][4], accC[4][4];
#pragma unroll
    for (int i = 0; i < 4; i++)
#pragma unroll
        for (int j = 0; j < 4; j++) { accM[i][j] = 0.f; accC[i][j] = 0.f; }

    for (int chk = 0; chk < NCHUNK; chk++) {
        const int k0 = chk * KC;
        const int c_base = k0 / 9;

        // ---- stage 1: raw x rows (hi/lo) + B weights into smem --------------
        for (int idx = tid; idx < 384; idx += 256) {
            int cc  = idx / 48;           // 0..7
            int row = (idx / 16) % 3;     // 0..2
            int seg = idx & 15;           // 16 segments of 4 px
            int y = h + row - 1;
            uint2 vh = make_uint2(0u, 0u), vl = make_uint2(0u, 0u);
            if ((unsigned)y < H_) {
                size_t off = ((size_t)(b * C_ + c_base + cc) * H_ + y) * W_ + seg * 4;
                vh = *reinterpret_cast<const uint2*>(g_xh + off);
                vl = *reinterpret_cast<const uint2*>(g_xl + off);
            }
            const __half* hp = reinterpret_cast<const __half*>(&vh);
            const __half* lp = reinterpret_cast<const __half*>(&vl);
#pragma unroll
            for (int t = 0; t < 4; t++) {
                rawh[cc][row][1 + seg * 4 + t] = hp[t];
                rawl[cc][row][1 + seg * 4 + t] = lp[t];
            }
            if (seg == 0)  { rawh[cc][row][0]  = __ushort_as_half(0);
                             rawl[cc][row][0]  = __ushort_as_half(0); }
            if (seg == 15) { rawh[cc][row][65] = __ushort_as_half(0);
                             rawl[cc][row][65] = __ushort_as_half(0); }
        }
        {   // B: n = tid/4, 16 k each (vector copies of pre-converted halves)
            int n  = tid >> 2;
            int kq = tid & 3;
            const uint4* ph = reinterpret_cast<const uint4*>(
                g_wh + (size_t)n * KTOT + k0 + kq * 16);
            const uint4* pl = reinterpret_cast<const uint4*>(
                g_wl + (size_t)n * KTOT + k0 + kq * 16);
            uint4 h0 = ph[0], h1 = ph[1], l0 = pl[0], l1 = pl[1];
            *reinterpret_cast<uint4*>(&Bsh[n][kq * 16])     = h0;
            *reinterpret_cast<uint4*>(&Bsh[n][kq * 16 + 8]) = h1;
            *reinterpret_cast<uint4*>(&Bsl[n][kq * 16])     = l0;
            *reinterpret_cast<uint4*>(&Bsl[n][kq * 16 + 8]) = l1;
        }
        __syncthreads();

        // ---- stage 2: build A^T[k][px] (shifted rows) -----------------------
        {
            int kk = tid >> 2;            // 0..63
            int pq = tid & 3;             // 16-px segment
            int k  = k0 + kk;
            int c  = k / 9;
            int r  = k - c * 9;
            int cloc = c - c_base;
            int kh = r / 3;
            int kw = r - kh * 3;
            const __half* rp  = &rawh[cloc][kh][pq * 16 + kw];
            const __half* rpl = &rawl[cloc][kh][pq * 16 + kw];
            uint32_t hv[8], lv[8];
#pragma unroll
            for (int j = 0; j < 8; j++) {
                hv[j] = pack2(rp[2 * j],  rp[2 * j + 1]);
                lv[j] = pack2(rpl[2 * j], rpl[2 * j + 1]);
            }
            uint4* dh = reinterpret_cast<uint4*>(&ATh[kk][pq * 16]);
            uint4* dl = reinterpret_cast<uint4*>(&ATl[kk][pq * 16]);
            dh[0] = make_uint4(hv[0], hv[1], hv[2], hv[3]);
            dh[1] = make_uint4(hv[4], hv[5], hv[6], hv[7]);
            dl[0] = make_uint4(lv[0], lv[1], lv[2], lv[3]);
            dl[1] = make_uint4(lv[4], lv[5], lv[6], lv[7]);
        }
        __syncthreads();

        // ---- mma over 4 k16-steps ------------------------------------------
#pragma unroll
        for (int ks = 0; ks < 4; ks++) {
            uint32_t aoff = (uint32_t)(((ks * 16 + lrow) * 72 + m0 + lcol8) * 2);
            uint32_t ah[4], al[4];
            ldsm4t(ah, sATh + aoff);
            ldsm4t(al, sATl + aoff);
#pragma unroll
            for (int hn = 0; hn < 2; hn++) {
                uint32_t boff = (uint32_t)(((n0 + hn * 16 + lrow) * 72
                                            + ks * 16 + lcol8) * 2);
                uint32_t bh[4], bl[4];
                ldsm4(bh, sBh + boff);
                ldsm4(bl, sBl + boff);
                int nt = hn * 2;
                mma16816(accM[nt],     ah, bh[0], bh[1]);
                mma16816(accM[nt + 1], ah, bh[2], bh[3]);
                mma16816(accC[nt],     ah, bl[0], bl[1]);
                mma16816(accC[nt + 1], ah, bl[2], bl[3]);
                mma16816(accC[nt],     al, bh[0], bh[1]);
                mma16816(accC[nt + 1], al, bh[2], bh[3]);
            }
        }
        __syncthreads();
    }

    // ---- epilogue: bias + relu, write g_feat -------------------------------
    const float inv = 1.f / 2048.f;
    const int gm   = lane >> 2;
    const int noff = (lane & 3) * 2;
#pragma unroll
    for (int nt = 0; nt < 4; nt++) {
        int n = n0 + nt * 8 + noff;
        float bias0 = __ldg(b1 + n);
        float bias1 = __ldg(b1 + n + 1);
        int px = m0 + gm;
        float v00 = accM[nt][0] + accC[nt][0] * inv + bias0;
        float v01 = accM[nt][1] + accC[nt][1] * inv + bias1;
        float v10 = accM[nt][2] + accC[nt][2] * inv + bias0;
        float v11 = accM[nt][3] + accC[nt][3] * inv + bias1;
        v00 = v00 > 0.f ? v00 : 0.f;
        v01 = v01 > 0.f ? v01 : 0.f;
        v10 = v10 > 0.f ? v10 : 0.f;
        v11 = v11 > 0.f ? v11 : 0.f;
        size_t base0 = ((size_t)(b * CMID + n)     * H_ + h) * W_;
        size_t base1 = ((size_t)(b * CMID + n + 1) * H_ + h) * W_;
        g_feat[base0 + px]     = v00;
        g_feat[base1 + px]     = v01;
        g_feat[base0 + px + 8] = v10;
        g_feat[base1 + px + 8] = v11;
    }
}

// ---------------------------------------------------------------------------
// Kernel 2: 1x1 conv (64 -> 100) + bias + softmax over 100 channels.
// ---------------------------------------------------------------------------
__global__ __launch_bounds__(256) void conv1x1_softmax_kernel(
    const float* __restrict__ w2, const float* __restrict__ b2)
{
    __shared__ float fs[64][64];
    __shared__ float w2s[NK][64];
    __shared__ float redm[4][64];
    __shared__ float reds[4][64];

    const int tid = threadIdx.x;
    const int jg  = tid >> 6;
    const int pix = tid & 63;

    const int b  = blockIdx.x >> 6;
    const int p0 = (blockIdx.x & 63) * 64;

    for (int idx = tid; idx < 64 * 64; idx += 256) {
        int k = idx >> 6, i = idx & 63;
        fs[k][i] = g_feat[(b * CMID + k) * (H_ * W_) + p0 + i];
    }
    for (int idx = tid; idx < NK * 64; idx += 256) {
        int j = idx >> 6, k = idx & 63;
        w2s[j][k] = w2[j * 64 + k];
    }
    __syncthreads();

    float acc[25];
#pragma unroll
    for (int jj = 0; jj < 25; jj++) acc[jj] = b2[jg * 25 + jj];

    for (int k = 0; k < 64; k++) {
        float f = fs[k][pix];
#pragma unroll
        for (int jj = 0; jj < 25; jj++)
            acc[jj] += f * w2s[jg * 25 + jj][k];
    }

    float lmax = acc[0];
#pragma unroll
    for (int jj = 1; jj < 25; jj++) lmax = fmaxf(lmax, acc[jj]);
    redm[jg][pix] = lmax;
    __syncthreads();
    float gmax = fmaxf(fmaxf(redm[0][pix], redm[1][pix]),
                       fmaxf(redm[2][pix], redm[3][pix]));
    float lsum = 0.f;
#pragma unroll
    for (int jj = 0; jj < 25; jj++) {
        acc[jj] = __expf(acc[jj] - gmax);
        lsum += acc[jj];
    }
    reds[jg][pix] = lsum;
    __syncthreads();
    float gsum = reds[0][pix] + reds[1][pix] + reds[2][pix] + reds[3][pix];
    float inv = 1.f / gsum;
#pragma unroll
    for (int jj = 0; jj < 25; jj++)
        g_kern[(b * NK + jg * 25 + jj) * (H_ * W_) + p0 + pix] = acc[jj] * inv;
}

// ---------------------------------------------------------------------------
// Kernel 3: reassembly + pixel shuffle (channel-split over grid.z).
// ---------------------------------------------------------------------------
__global__ __launch_bounds__(128) void reassembly_kernel(
    const float* __restrict__ x, float* __restrict__ out)
{
    __shared__ float xs[32][12][12];

    const int tid = threadIdx.x;
    const int sg  = tid >> 6;
    const int pix = tid & 63;
    const int py  = pix >> 3;
    const int px  = pix & 7;

    const int x0 = blockIdx.x * 8;
    const int y0 = blockIdx.y * 8;
    const int b  = blockIdx.z >> 2;
    const int sp = blockIdx.z & 3;
    const int gy = y0 + py, gx = x0 + px;

    float kreg[2][25];
#pragma unroll
    for (int s2 = 0; s2 < 2; s2++) {
        int s = sg * 2 + s2;
#pragma unroll
        for (int k = 0; k < 25; k++)
            kreg[s2][k] = g_kern[((b * NK + s * 25 + k) * H_ + gy) * W_ + gx];
    }

    for (int c0 = sp * CSPL; c0 < sp * CSPL + CSPL; c0 += 32) {
        __syncthreads();
        for (int idx = tid; idx < 32 * 144; idx += 128) {
            int cc  = idx / 144;
            int r   = (idx % 144) / 12;
            int col = idx % 12;
            int yy = y0 + r - 2;
            int xx = x0 + col - 2;
            float v = 0.f;
            if (yy >= 0 && yy < H_ && xx >= 0 && xx < W_)
                v = x[((b * C_ + c0 + cc) * H_ + yy) * W_ + xx];
            xs[cc][r][col] = v;
        }
        __syncthreads();

#pragma unroll 2
        for (int cc = 0; cc < 32; cc += 2) {
            float a00 = 0.f, a10 = 0.f;
            float a01 = 0.f, a11 = 0.f;
#pragma unroll
            for (int kh = 0; kh < 5; kh++)
#pragma unroll
                for (int kw = 0; kw < 5; kw++) {
                    int k = kh * 5 + kw;
                    float v0 = xs[cc][py + kh][px + kw];
                    float v1 = xs[cc + 1][py + kh][px + kw];
                    a00 += kreg[0][k] * v0;
                    a10 += kreg[1][k] * v0;
                    a01 += kreg[0][k] * v1;
                    a11 += kreg[1][k] * v1;
                }
            int c = c0 + cc;
            int q4 = c >> 2;
            int a  = (c >> 1) & 1;
            int oy = 2 * gy + a;
            int ox = 2 * gx;
#pragma unroll
            for (int s2 = 0; s2 < 2; s2++) {
                int s = sg * 2 + s2;
                int q = s * 64 + q4;
                float2 v;
                v.x = (s2 == 0) ? a00 : a10;
                v.y = (s2 == 0) ? a01 : a11;
                *reinterpret_cast<float2*>(
                    &out[((size_t)(b * C_ + q) * 128 + oy) * 128 + ox]) = v;
            }
        }
    }
}

// ---------------------------------------------------------------------------
extern "C" void kernel_launch(void* const* d_in, const int* in_sizes, int n_in,
                              void* d_out, int out_size)
{
    const float* x  = (const float*)d_in[0];
    const float* w1 = (const float*)d_in[1];
    const float* b1 = (const float*)d_in[2];
    const float* w2 = (const float*)d_in[3];
    const float* b2 = (const float*)d_in[4];
    float* out = (float*)d_out;

    convert_kernel<<<1024, 256>>>(x, w1);
    conv3x3_hmma_kernel<<<B_ * H_, 256>>>(b1);
    conv1x1_softmax_kernel<<<B_ * (H_ * W_) / 64, 256>>>(w2, b2);

    dim3 gsplit(W_ / 8, H_ / 8, B_ * NSPLIT);
    reassembly_kernel<<<gsplit, 128>>>(x, out);
}

// round 5
// speedup vs baseline: 2.4435x; 1.1477x over previous
#include <cuda_runtime.h>
#include <cuda_fp16.h>
#include <cstdint>

// CARAFE: conv3x3(+bias+relu) via fp16 split-precision mma.sync implicit GEMM,
// then conv1x1+softmax, then 5x5 reassembly + pixel_shuffle(2).
// x(4,256,64,64) w1(64,256,3,3) b1(64) w2(100,64) b2(100) -> out(4,256,128,128)

#define B_   4
#define C_   256
#define H_   64
#define W_   64
#define CMID 64
#define NK   100
#define NSPLIT 4
#define CSPL (C_ / NSPLIT)

#define KTOT   (C_ * 9)     // 2304
#define KC     64           // k per staged chunk
#define NCHUNK (KTOT / KC)  // 36

#define NX (B_ * C_ * H_ * W_)   // 4194304
#define NW (CMID * KTOT)         // 147456

// scratch
__device__ float  g_feat[B_ * CMID * H_ * W_];
__device__ float  g_kern[B_ * NK * H_ * W_];
__device__ __half g_xh[NX];
__device__ __half g_xl[NX];     // 2048*(x - hi)
__device__ __half g_wh[NW];
__device__ __half g_wl[NW];     // 2048*(w - hi)

__device__ __forceinline__ uint32_t s2u(const void* p) {
    uint32_t a;
    asm("{ .reg .u64 t; cvta.to.shared.u64 t, %1; cvt.u32.u64 %0, t; }"
        : "=r"(a) : "l"(p));
    return a;
}
__device__ __forceinline__ void ldsm4(uint32_t* r, uint32_t addr) {
    asm volatile("ldmatrix.sync.aligned.m8n8.x4.shared.b16 {%0,%1,%2,%3}, [%4];"
                 : "=r"(r[0]), "=r"(r[1]), "=r"(r[2]), "=r"(r[3]) : "r"(addr));
}
__device__ __forceinline__ void ldsm4t(uint32_t* r, uint32_t addr) {
    asm volatile("ldmatrix.sync.aligned.m8n8.x4.trans.shared.b16 {%0,%1,%2,%3}, [%4];"
                 : "=r"(r[0]), "=r"(r[1]), "=r"(r[2]), "=r"(r[3]) : "r"(addr));
}
__device__ __forceinline__ void mma16816(float* d, const uint32_t* a,
                                         uint32_t b0, uint32_t b1) {
    asm volatile(
        "mma.sync.aligned.m16n8k16.row.col.f32.f16.f16.f32 "
        "{%0,%1,%2,%3}, {%4,%5,%6,%7}, {%8,%9}, {%0,%1,%2,%3};"
        : "+f"(d[0]), "+f"(d[1]), "+f"(d[2]), "+f"(d[3])
        : "r"(a[0]), "r"(a[1]), "r"(a[2]), "r"(a[3]), "r"(b0), "r"(b1));
}
__device__ __forceinline__ uint32_t pack2(__half a, __half b) {
    return (uint32_t)__half_as_ushort(a) | ((uint32_t)__half_as_ushort(b) << 16);
}

// ---------------------------------------------------------------------------
// Kernel 0: fp16 hi/lo conversion of x and w1 (lo scaled by 2048).
// ---------------------------------------------------------------------------
__global__ void convert_kernel(const float* __restrict__ x,
                               const float* __restrict__ w1)
{
    for (int i = blockIdx.x * blockDim.x + threadIdx.x; i < NX;
         i += gridDim.x * blockDim.x) {
        float v = x[i];
        __half h = __float2half_rn(v);
        g_xh[i] = h;
        g_xl[i] = __float2half_rn((v - __half2float(h)) * 2048.f);
        if (i < NW) {
            float w = w1[i];
            __half wh = __float2half_rn(w);
            g_wh[i] = wh;
            g_wl[i] = __float2half_rn((w - __half2float(wh)) * 2048.f);
        }
    }
}

// ---------------------------------------------------------------------------
// Kernel 1: conv3x3 + bias + ReLU as fp16 HMMA implicit GEMM.
// grid = 256 (b,h = one image row, M=64 pixels); block = 256 (8 warps).
// 3-pass split: D = Ah*Bh + (Ah*Bl' + Al'*Bh)/2048.
// ---------------------------------------------------------------------------
__global__ __launch_bounds__(256, 2) void conv3x3_hmma_kernel(
    const float* __restrict__ b1)
{
    __shared__ __half ATh[KC][72];      // [k][pixel]
    __shared__ __half ATl[KC][72];
    __shared__ __half Bsh[CMID][72];    // [n][k]
    __shared__ __half Bsl[CMID][72];
    __shared__ __half rawh[8][3][68];   // padded raw rows: col t = x px (t-1)
    __shared__ __half rawl[8][3][68];

    const int tid  = threadIdx.x;
    const int lane = tid & 31;
    const int wid  = tid >> 5;
    const int b    = blockIdx.x >> 6;
    const int h    = blockIdx.x & 63;

    const int m0 = (wid & 3) * 16;
    const int n0 = (wid >> 2) * 32;

    const int lrow  = (lane & 7) + ((lane >> 4) & 1) * 8;
    const int lcol8 = ((lane >> 3) & 1) * 8;

    const uint32_t sATh = s2u(ATh), sATl = s2u(ATl);
    const uint32_t sBh  = s2u(Bsh), sBl  = s2u(Bsl);

    float accM[4][4], accC[4][4];
#pragma unroll
    for (int i = 0; i < 4; i++)
#pragma unroll
        for (int j = 0; j < 4; j++) { accM[i][j] = 0.f; accC[i][j] = 0.f; }

    for (int chk = 0; chk < NCHUNK; chk++) {
        const int k0 = chk * KC;
        const int c_base = k0 / 9;

        for (int idx = tid; idx < 384; idx += 256) {
            int cc  = idx / 48;
            int row = (idx / 16) % 3;
            int seg = idx & 15;
            int y = h + row - 1;
            uint2 vh = make_uint2(0u, 0u), vl = make_uint2(0u, 0u);
            if ((unsigned)y < H_) {
                size_t off = ((size_t)(b * C_ + c_base + cc) * H_ + y) * W_ + seg * 4;
                vh = *reinterpret_cast<const uint2*>(g_xh + off);
                vl = *reinterpret_cast<const uint2*>(g_xl + off);
            }
            const __half* hp = reinterpret_cast<const __half*>(&vh);
            const __half* lp = reinterpret_cast<const __half*>(&vl);
#pragma unroll
            for (int t = 0; t < 4; t++) {
                rawh[cc][row][1 + seg * 4 + t] = hp[t];
                rawl[cc][row][1 + seg * 4 + t] = lp[t];
            }
            if (seg == 0)  { rawh[cc][row][0]  = __ushort_as_half(0);
                             rawl[cc][row][0]  = __ushort_as_half(0); }
            if (seg == 15) { rawh[cc][row][65] = __ushort_as_half(0);
                             rawl[cc][row][65] = __ushort_as_half(0); }
        }
        {
            int n  = tid >> 2;
            int kq = tid & 3;
            const uint4* ph = reinterpret_cast<const uint4*>(
                g_wh + (size_t)n * KTOT + k0 + kq * 16);
            const uint4* pl = reinterpret_cast<const uint4*>(
                g_wl + (size_t)n * KTOT + k0 + kq * 16);
            uint4 h0 = ph[0], h1 = ph[1], l0 = pl[0], l1 = pl[1];
            *reinterpret_cast<uint4*>(&Bsh[n][kq * 16])     = h0;
            *reinterpret_cast<uint4*>(&Bsh[n][kq * 16 + 8]) = h1;
            *reinterpret_cast<uint4*>(&Bsl[n][kq * 16])     = l0;
            *reinterpret_cast<uint4*>(&Bsl[n][kq * 16 + 8]) = l1;
        }
        __syncthreads();

        {
            int kk = tid >> 2;
            int pq = tid & 3;
            int k  = k0 + kk;
            int c  = k / 9;
            int r  = k - c * 9;
            int cloc = c - c_base;
            int kh = r / 3;
            int kw = r - kh * 3;
            const __half* rp  = &rawh[cloc][kh][pq * 16 + kw];
            const __half* rpl = &rawl[cloc][kh][pq * 16 + kw];
            uint32_t hv[8], lv[8];
#pragma unroll
            for (int j = 0; j < 8; j++) {
                hv[j] = pack2(rp[2 * j],  rp[2 * j + 1]);
                lv[j] = pack2(rpl[2 * j], rpl[2 * j + 1]);
            }
            uint4* dh = reinterpret_cast<uint4*>(&ATh[kk][pq * 16]);
            uint4* dl = reinterpret_cast<uint4*>(&ATl[kk][pq * 16]);
            dh[0] = make_uint4(hv[0], hv[1], hv[2], hv[3]);
            dh[1] = make_uint4(hv[4], hv[5], hv[6], hv[7]);
            dl[0] = make_uint4(lv[0], lv[1], lv[2], lv[3]);
            dl[1] = make_uint4(lv[4], lv[5], lv[6], lv[7]);
        }
        __syncthreads();

#pragma unroll
        for (int ks = 0; ks < 4; ks++) {
            uint32_t aoff = (uint32_t)(((ks * 16 + lrow) * 72 + m0 + lcol8) * 2);
            uint32_t ah[4], al[4];
            ldsm4t(ah, sATh + aoff);
            ldsm4t(al, sATl + aoff);
#pragma unroll
            for (int hn = 0; hn < 2; hn++) {
                uint32_t boff = (uint32_t)(((n0 + hn * 16 + lrow) * 72
                                            + ks * 16 + lcol8) * 2);
                uint32_t bh[4], bl[4];
                ldsm4(bh, sBh + boff);
                ldsm4(bl, sBl + boff);
                int nt = hn * 2;
                mma16816(accM[nt],     ah, bh[0], bh[1]);
                mma16816(accM[nt + 1], ah, bh[2], bh[3]);
                mma16816(accC[nt],     ah, bl[0], bl[1]);
                mma16816(accC[nt + 1], ah, bl[2], bl[3]);
                mma16816(accC[nt],     al, bh[0], bh[1]);
                mma16816(accC[nt + 1], al, bh[2], bh[3]);
            }
        }
        __syncthreads();
    }

    const float inv = 1.f / 2048.f;
    const int gm   = lane >> 2;
    const int noff = (lane & 3) * 2;
#pragma unroll
    for (int nt = 0; nt < 4; nt++) {
        int n = n0 + nt * 8 + noff;
        float bias0 = __ldg(b1 + n);
        float bias1 = __ldg(b1 + n + 1);
        int px = m0 + gm;
        float v00 = accM[nt][0] + accC[nt][0] * inv + bias0;
        float v01 = accM[nt][1] + accC[nt][1] * inv + bias1;
        float v10 = accM[nt][2] + accC[nt][2] * inv + bias0;
        float v11 = accM[nt][3] + accC[nt][3] * inv + bias1;
        v00 = v00 > 0.f ? v00 : 0.f;
        v01 = v01 > 0.f ? v01 : 0.f;
        v10 = v10 > 0.f ? v10 : 0.f;
        v11 = v11 > 0.f ? v11 : 0.f;
        size_t base0 = ((size_t)(b * CMID + n)     * H_ + h) * W_;
        size_t base1 = ((size_t)(b * CMID + n + 1) * H_ + h) * W_;
        g_feat[base0 + px]     = v00;
        g_feat[base1 + px]     = v01;
        g_feat[base0 + px + 8] = v10;
        g_feat[base1 + px + 8] = v11;
    }
}

// ---------------------------------------------------------------------------
// Kernel 2: 1x1 conv (64 -> 100) + bias + softmax over 100 channels.
// ---------------------------------------------------------------------------
__global__ __launch_bounds__(256) void conv1x1_softmax_kernel(
    const float* __restrict__ w2, const float* __restrict__ b2)
{
    __shared__ float fs[64][64];
    __shared__ float w2s[NK][64];
    __shared__ float redm[4][64];
    __shared__ float reds[4][64];

    const int tid = threadIdx.x;
    const int jg  = tid >> 6;
    const int pix = tid & 63;

    const int b  = blockIdx.x >> 6;
    const int p0 = (blockIdx.x & 63) * 64;

    for (int idx = tid; idx < 64 * 64; idx += 256) {
        int k = idx >> 6, i = idx & 63;
        fs[k][i] = g_feat[(b * CMID + k) * (H_ * W_) + p0 + i];
    }
    for (int idx = tid; idx < NK * 64; idx += 256) {
        int j = idx >> 6, k = idx & 63;
        w2s[j][k] = w2[j * 64 + k];
    }
    __syncthreads();

    float acc[25];
#pragma unroll
    for (int jj = 0; jj < 25; jj++) acc[jj] = b2[jg * 25 + jj];

    for (int k = 0; k < 64; k++) {
        float f = fs[k][pix];
#pragma unroll
        for (int jj = 0; jj < 25; jj++)
            acc[jj] += f * w2s[jg * 25 + jj][k];
    }

    float lmax = acc[0];
#pragma unroll
    for (int jj = 1; jj < 25; jj++) lmax = fmaxf(lmax, acc[jj]);
    redm[jg][pix] = lmax;
    __syncthreads();
    float gmax = fmaxf(fmaxf(redm[0][pix], redm[1][pix]),
                       fmaxf(redm[2][pix], redm[3][pix]));
    float lsum = 0.f;
#pragma unroll
    for (int jj = 0; jj < 25; jj++) {
        acc[jj] = __expf(acc[jj] - gmax);
        lsum += acc[jj];
    }
    reds[jg][pix] = lsum;
    __syncthreads();
    float gsum = reds[0][pix] + reds[1][pix] + reds[2][pix] + reds[3][pix];
    float inv = 1.f / gsum;
#pragma unroll
    for (int jj = 0; jj < 25; jj++)
        g_kern[(b * NK + jg * 25 + jj) * (H_ * W_) + p0 + pix] = acc[jj] * inv;
}

// ---------------------------------------------------------------------------
// Kernel 3: reassembly + pixel shuffle.
// Each thread: one pixel, ALL 4 s values (kreg[4][25] in regs), 2 channels per
// step -> 50 LDS per 200 FFMA. Row stride 24 floats => conflict-free LDS.
// Block 128 = 2 channel-groups x 64 pixels (8x8 tile). grid (8,8,B*NSPLIT).
// ---------------------------------------------------------------------------
__global__ __launch_bounds__(128, 2) void reassembly_kernel(
    const float* __restrict__ x, float* __restrict__ out)
{
    __shared__ float xs[32][12][24];    // stride 24: banks py*24+px all distinct

    const int tid = threadIdx.x;
    const int cg  = tid >> 6;           // 0..1 -> channels [cg*16, cg*16+16)
    const int pix = tid & 63;
    const int py  = pix >> 3;
    const int px  = pix & 7;

    const int x0 = blockIdx.x * 8;
    const int y0 = blockIdx.y * 8;
    const int b  = blockIdx.z >> 2;
    const int sp = blockIdx.z & 3;
    const int gy = y0 + py, gx = x0 + px;

    // all 4 s weight sets for this pixel
    float kreg[4][25];
#pragma unroll
    for (int s = 0; s < 4; s++)
#pragma unroll
        for (int k = 0; k < 25; k++)
            kreg[s][k] = g_kern[((b * NK + s * 25 + k) * H_ + gy) * W_ + gx];

    for (int c0 = sp * CSPL; c0 < sp * CSPL + CSPL; c0 += 32) {
        __syncthreads();
        // stage 32 channels x 12x12 (halo 2), physical row stride 24
        for (int idx = tid; idx < 32 * 144; idx += 128) {
            int cc  = idx / 144;
            int r   = (idx % 144) / 12;
            int col = idx % 12;
            int yy = y0 + r - 2;
            int xx = x0 + col - 2;
            float v = 0.f;
            if (yy >= 0 && yy < H_ && xx >= 0 && xx < W_)
                v = x[((b * C_ + c0 + cc) * H_ + yy) * W_ + xx];
            xs[cc][r][col] = v;
        }
        __syncthreads();

#pragma unroll 2
        for (int cc2 = 0; cc2 < 16; cc2 += 2) {
            int ch = cg * 16 + cc2;
            float a0[4], a1[4];
#pragma unroll
            for (int s = 0; s < 4; s++) { a0[s] = 0.f; a1[s] = 0.f; }
#pragma unroll
            for (int kh = 0; kh < 5; kh++)
#pragma unroll
                for (int kw = 0; kw < 5; kw++) {
                    int k = kh * 5 + kw;
                    float v0 = xs[ch][py + kh][px + kw];
                    float v1 = xs[ch + 1][py + kh][px + kw];
#pragma unroll
                    for (int s = 0; s < 4; s++) {
                        a0[s] += kreg[s][k] * v0;
                        a1[s] += kreg[s][k] * v1;
                    }
                }
            int c  = c0 + ch;             // even
            int q4 = c >> 2;
            int a  = (c >> 1) & 1;
            int oy = 2 * gy + a;
            int ox = 2 * gx;
#pragma unroll
            for (int s = 0; s < 4; s++) {
                float2 v;
                v.x = a0[s];
                v.y = a1[s];
                *reinterpret_cast<float2*>(
                    &out[((size_t)(b * C_ + s * 64 + q4) * 128 + oy) * 128 + ox]) = v;
            }
        }
    }
}

// ---------------------------------------------------------------------------
extern "C" void kernel_launch(void* const* d_in, const int* in_sizes, int n_in,
                              void* d_out, int out_size)
{
    const float* x  = (const float*)d_in[0];
    const float* w1 = (const float*)d_in[1];
    const float* b1 = (const float*)d_in[2];
    const float* w2 = (const float*)d_in[3];
    const float* b2 = (const float*)d_in[4];
    float* out = (float*)d_out;

    convert_kernel<<<1024, 256>>>(x, w1);
    conv3x3_hmma_kernel<<<B_ * H_, 256>>>(b1);
    conv1x1_softmax_kernel<<<B_ * (H_ * W_) / 64, 256>>>(w2, b2);

    dim3 gsplit(W_ / 8, H_ / 8, B_ * NSPLIT);
    reassembly_kernel<<<gsplit, 128>>>(x, out);
}

// round 6
// speedup vs baseline: 3.1401x; 1.2851x over previous
#include <cuda_runtime.h>
#include <cuda_fp16.h>
#include <cstdint>

// CARAFE: conv3x3 via single-pass fp16 mma.sync implicit GEMM (K-split x2),
// combine+bias+relu fused into conv1x1+softmax, then 5x5 reassembly + shuffle.
// x(4,256,64,64) w1(64,256,3,3) b1(64) w2(100,64) b2(100) -> out(4,256,128,128)

#define B_   4
#define C_   256
#define H_   64
#define W_   64
#define CMID 64
#define NK   100
#define NSPLIT 4
#define CSPL (C_ / NSPLIT)

#define KTOT   (C_ * 9)     // 2304
#define KC     64           // k per staged chunk
#define NCHUNK (KTOT / KC)  // 36
#define KSPLIT 2
#define CHPS   (NCHUNK / KSPLIT)  // 18 chunks per CTA

#define NX (B_ * C_ * H_ * W_)   // 4194304
#define NW (CMID * KTOT)         // 147456

// scratch
__device__ float  g_feat_part[KSPLIT * B_ * CMID * H_ * W_];  // 8 MB
__device__ float  g_kern[B_ * NK * H_ * W_];
__device__ __half g_xh[NX];
__device__ __half g_wh[NW];

__device__ __forceinline__ uint32_t s2u(const void* p) {
    uint32_t a;
    asm("{ .reg .u64 t; cvta.to.shared.u64 t, %1; cvt.u32.u64 %0, t; }"
        : "=r"(a) : "l"(p));
    return a;
}
__device__ __forceinline__ void ldsm4(uint32_t* r, uint32_t addr) {
    asm volatile("ldmatrix.sync.aligned.m8n8.x4.shared.b16 {%0,%1,%2,%3}, [%4];"
                 : "=r"(r[0]), "=r"(r[1]), "=r"(r[2]), "=r"(r[3]) : "r"(addr));
}
__device__ __forceinline__ void ldsm4t(uint32_t* r, uint32_t addr) {
    asm volatile("ldmatrix.sync.aligned.m8n8.x4.trans.shared.b16 {%0,%1,%2,%3}, [%4];"
                 : "=r"(r[0]), "=r"(r[1]), "=r"(r[2]), "=r"(r[3]) : "r"(addr));
}
__device__ __forceinline__ void mma16816(float* d, const uint32_t* a,
                                         uint32_t b0, uint32_t b1) {
    asm volatile(
        "mma.sync.aligned.m16n8k16.row.col.f32.f16.f16.f32 "
        "{%0,%1,%2,%3}, {%4,%5,%6,%7}, {%8,%9}, {%0,%1,%2,%3};"
        : "+f"(d[0]), "+f"(d[1]), "+f"(d[2]), "+f"(d[3])
        : "r"(a[0]), "r"(a[1]), "r"(a[2]), "r"(a[3]), "r"(b0), "r"(b1));
}
__device__ __forceinline__ uint32_t pack2(__half a, __half b) {
    return (uint32_t)__half_as_ushort(a) | ((uint32_t)__half_as_ushort(b) << 16);
}

// ---------------------------------------------------------------------------
// Kernel 0: fp16 conversion of x and w1.
// ---------------------------------------------------------------------------
__global__ void convert_kernel(const float* __restrict__ x,
                               const float* __restrict__ w1)
{
    for (int i = blockIdx.x * blockDim.x + threadIdx.x; i < NX;
         i += gridDim.x * blockDim.x) {
        g_xh[i] = __float2half_rn(x[i]);
        if (i < NW) g_wh[i] = __float2half_rn(w1[i]);
    }
}

// ---------------------------------------------------------------------------
// Kernel 1: conv3x3 partial (18 K-chunks) as fp16 HMMA implicit GEMM.
// grid = 512: blockIdx.x -> b (>>7), h ((x>>1)&63), ksplit (x&1).
// block = 256 (8 warps): warp -> m0 = 16*(wid&3), n0 = 32*(wid>>2).
// ---------------------------------------------------------------------------
__global__ __launch_bounds__(256, 3) void conv3x3_hmma_kernel()
{
    __shared__ __half ATh[KC][72];      // [k][pixel]
    __shared__ __half Bsh[CMID][72];    // [n][k]
    __shared__ __half rawh[8][3][68];   // padded raw rows: col t = x px (t-1)

    const int tid  = threadIdx.x;
    const int lane = tid & 31;
    const int wid  = tid >> 5;
    const int b    = blockIdx.x >> 7;
    const int h    = (blockIdx.x >> 1) & 63;
    const int ksp  = blockIdx.x & 1;

    const int m0 = (wid & 3) * 16;
    const int n0 = (wid >> 2) * 32;

    const int lrow  = (lane & 7) + ((lane >> 4) & 1) * 8;
    const int lcol8 = ((lane >> 3) & 1) * 8;

    const uint32_t sATh = s2u(ATh);
    const uint32_t sBh  = s2u(Bsh);

    float accM[4][4];
#pragma unroll
    for (int i = 0; i < 4; i++)
#pragma unroll
        for (int j = 0; j < 4; j++) accM[i][j] = 0.f;

    for (int chk = ksp * CHPS; chk < (ksp + 1) * CHPS; chk++) {
        const int k0 = chk * KC;
        const int c_base = k0 / 9;

        // ---- stage 1: raw x rows + B weights into smem ----------------------
        for (int idx = tid; idx < 384; idx += 256) {
            int cc  = idx / 48;           // 0..7
            int row = (idx / 16) % 3;     // 0..2
            int seg = idx & 15;           // 16 segments of 4 px
            int y = h + row - 1;
            uint2 vh = make_uint2(0u, 0u);
            if ((unsigned)y < H_) {
                size_t off = ((size_t)(b * C_ + c_base + cc) * H_ + y) * W_ + seg * 4;
                vh = *reinterpret_cast<const uint2*>(g_xh + off);
            }
            const __half* hp = reinterpret_cast<const __half*>(&vh);
#pragma unroll
            for (int t = 0; t < 4; t++)
                rawh[cc][row][1 + seg * 4 + t] = hp[t];
            if (seg == 0)  rawh[cc][row][0]  = __ushort_as_half(0);
            if (seg == 15) rawh[cc][row][65] = __ushort_as_half(0);
        }
        {   // B: n = tid/4, 16 k each
            int n  = tid >> 2;
            int kq = tid & 3;
            const uint4* ph = reinterpret_cast<const uint4*>(
                g_wh + (size_t)n * KTOT + k0 + kq * 16);
            uint4 h0 = ph[0], h1 = ph[1];
            *reinterpret_cast<uint4*>(&Bsh[n][kq * 16])     = h0;
            *reinterpret_cast<uint4*>(&Bsh[n][kq * 16 + 8]) = h1;
        }
        __syncthreads();

        // ---- stage 2: build A^T[k][px] (shifted rows) -----------------------
        {
            int kk = tid >> 2;            // 0..63
            int pq = tid & 3;             // 16-px segment
            int k  = k0 + kk;
            int c  = k / 9;
            int r  = k - c * 9;
            int cloc = c - c_base;
            int kh = r / 3;
            int kw = r - kh * 3;
            const __half* rp = &rawh[cloc][kh][pq * 16 + kw];
            uint32_t hv[8];
#pragma unroll
            for (int j = 0; j < 8; j++)
                hv[j] = pack2(rp[2 * j], rp[2 * j + 1]);
            uint4* dh = reinterpret_cast<uint4*>(&ATh[kk][pq * 16]);
            dh[0] = make_uint4(hv[0], hv[1], hv[2], hv[3]);
            dh[1] = make_uint4(hv[4], hv[5], hv[6], hv[7]);
        }
        __syncthreads();

        // ---- mma over 4 k16-steps ------------------------------------------
#pragma unroll
        for (int ks = 0; ks < 4; ks++) {
            uint32_t aoff = (uint32_t)(((ks * 16 + lrow) * 72 + m0 + lcol8) * 2);
            uint32_t ah[4];
            ldsm4t(ah, sATh + aoff);
#pragma unroll
            for (int hn = 0; hn < 2; hn++) {
                uint32_t boff = (uint32_t)(((n0 + hn * 16 + lrow) * 72
                                            + ks * 16 + lcol8) * 2);
                uint32_t bh[4];
                ldsm4(bh, sBh + boff);
                int nt = hn * 2;
                mma16816(accM[nt],     ah, bh[0], bh[1]);
                mma16816(accM[nt + 1], ah, bh[2], bh[3]);
            }
        }
        __syncthreads();
    }

    // ---- epilogue: write raw partials (combine fused into kernel 2) --------
    const int gm   = lane >> 2;
    const int noff = (lane & 3) * 2;
#pragma unroll
    for (int nt = 0; nt < 4; nt++) {
        int n = n0 + nt * 8 + noff;
        int px = m0 + gm;
        size_t base0 = (((size_t)(ksp * B_ + b) * CMID + n)     * H_ + h) * W_;
        size_t base1 = (((size_t)(ksp * B_ + b) * CMID + n + 1) * H_ + h) * W_;
        g_feat_part[base0 + px]     = accM[nt][0];
        g_feat_part[base1 + px]     = accM[nt][1];
        g_feat_part[base0 + px + 8] = accM[nt][2];
        g_feat_part[base1 + px + 8] = accM[nt][3];
    }
}

// ---------------------------------------------------------------------------
// Kernel 2: combine K-split partials + bias + relu, 1x1 conv (64->100),
// bias + softmax over 100 channels.
// ---------------------------------------------------------------------------
__global__ __launch_bounds__(256) void conv1x1_softmax_kernel(
    const float* __restrict__ b1,
    const float* __restrict__ w2, const float* __restrict__ b2)
{
    __shared__ float fs[64][64];
    __shared__ float w2s[NK][64];
    __shared__ float redm[4][64];
    __shared__ float reds[4][64];

    const int tid = threadIdx.x;
    const int jg  = tid >> 6;
    const int pix = tid & 63;

    const int b  = blockIdx.x >> 6;
    const int p0 = (blockIdx.x & 63) * 64;

    for (int idx = tid; idx < 64 * 64; idx += 256) {
        int k = idx >> 6, i = idx & 63;
        float v = b1[k];
#pragma unroll
        for (int p = 0; p < KSPLIT; p++)
            v += g_feat_part[((size_t)(p * B_ + b) * CMID + k) * (H_ * W_) + p0 + i];
        fs[k][i] = v > 0.f ? v : 0.f;
    }
    for (int idx = tid; idx < NK * 64; idx += 256) {
        int j = idx >> 6, k = idx & 63;
        w2s[j][k] = w2[j * 64 + k];
    }
    __syncthreads();

    float acc[25];
#pragma unroll
    for (int jj = 0; jj < 25; jj++) acc[jj] = b2[jg * 25 + jj];

    for (int k = 0; k < 64; k++) {
        float f = fs[k][pix];
#pragma unroll
        for (int jj = 0; jj < 25; jj++)
            acc[jj] += f * w2s[jg * 25 + jj][k];
    }

    float lmax = acc[0];
#pragma unroll
    for (int jj = 1; jj < 25; jj++) lmax = fmaxf(lmax, acc[jj]);
    redm[jg][pix] = lmax;
    __syncthreads();
    float gmax = fmaxf(fmaxf(redm[0][pix], redm[1][pix]),
                       fmaxf(redm[2][pix], redm[3][pix]));
    float lsum = 0.f;
#pragma unroll
    for (int jj = 0; jj < 25; jj++) {
        acc[jj] = __expf(acc[jj] - gmax);
        lsum += acc[jj];
    }
    reds[jg][pix] = lsum;
    __syncthreads();
    float gsum = reds[0][pix] + reds[1][pix] + reds[2][pix] + reds[3][pix];
    float inv = 1.f / gsum;
#pragma unroll
    for (int jj = 0; jj < 25; jj++)
        g_kern[(b * NK + jg * 25 + jj) * (H_ * W_) + p0 + pix] = acc[jj] * inv;
}

// ---------------------------------------------------------------------------
// Kernel 3: reassembly + pixel shuffle.
// Each thread: one pixel, ALL 4 s values (kreg[4][25] in regs), 2 channels per
// step -> 50 LDS per 200 FFMA. Row stride 24 floats => conflict-free LDS.
// ---------------------------------------------------------------------------
__global__ __launch_bounds__(128, 2) void reassembly_kernel(
    const float* __restrict__ x, float* __restrict__ out)
{
    __shared__ float xs[32][12][24];

    const int tid = threadIdx.x;
    const int cg  = tid >> 6;           // 0..1 -> channels [cg*16, cg*16+16)
    const int pix = tid & 63;
    const int py  = pix >> 3;
    const int px  = pix & 7;

    const int x0 = blockIdx.x * 8;
    const int y0 = blockIdx.y * 8;
    const int b  = blockIdx.z >> 2;
    const int sp = blockIdx.z & 3;
    const int gy = y0 + py, gx = x0 + px;

    float kreg[4][25];
#pragma unroll
    for (int s = 0; s < 4; s++)
#pragma unroll
        for (int k = 0; k < 25; k++)
            kreg[s][k] = g_kern[((b * NK + s * 25 + k) * H_ + gy) * W_ + gx];

    for (int c0 = sp * CSPL; c0 < sp * CSPL + CSPL; c0 += 32) {
        __syncthreads();
        for (int idx = tid; idx < 32 * 144; idx += 128) {
            int cc  = idx / 144;
            int r   = (idx % 144) / 12;
            int col = idx % 12;
            int yy = y0 + r - 2;
            int xx = x0 + col - 2;
            float v = 0.f;
            if (yy >= 0 && yy < H_ && xx >= 0 && xx < W_)
                v = x[((b * C_ + c0 + cc) * H_ + yy) * W_ + xx];
            xs[cc][r][col] = v;
        }
        __syncthreads();

#pragma unroll 2
        for (int cc2 = 0; cc2 < 16; cc2 += 2) {
            int ch = cg * 16 + cc2;
            float a0[4], a1[4];
#pragma unroll
            for (int s = 0; s < 4; s++) { a0[s] = 0.f; a1[s] = 0.f; }
#pragma unroll
            for (int kh = 0; kh < 5; kh++)
#pragma unroll
                for (int kw = 0; kw < 5; kw++) {
                    int k = kh * 5 + kw;
                    float v0 = xs[ch][py + kh][px + kw];
                    float v1 = xs[ch + 1][py + kh][px + kw];
#pragma unroll
                    for (int s = 0; s < 4; s++) {
                        a0[s] += kreg[s][k] * v0;
                        a1[s] += kreg[s][k] * v1;
                    }
                }
            int c  = c0 + ch;
            int q4 = c >> 2;
            int a  = (c >> 1) & 1;
            int oy = 2 * gy + a;
            int ox = 2 * gx;
#pragma unroll
            for (int s = 0; s < 4; s++) {
                float2 v;
                v.x = a0[s];
                v.y = a1[s];
                *reinterpret_cast<float2*>(
                    &out[((size_t)(b * C_ + s * 64 + q4) * 128 + oy) * 128 + ox]) = v;
            }
        }
    }
}

// ---------------------------------------------------------------------------
extern "C" void kernel_launch(void* const* d_in, const int* in_sizes, int n_in,
                              void* d_out, int out_size)
{
    const float* x  = (const float*)d_in[0];
    const float* w1 = (const float*)d_in[1];
    const float* b1 = (const float*)d_in[2];
    const float* w2 = (const float*)d_in[3];
    const float* b2 = (const float*)d_in[4];
    float* out = (float*)d_out;

    convert_kernel<<<1024, 256>>>(x, w1);
    conv3x3_hmma_kernel<<<B_ * H_ * KSPLIT, 256>>>();
    conv1x1_softmax_kernel<<<B_ * (H_ * W_) / 64, 256>>>(b1, w2, b2);

    dim3 gsplit(W_ / 8, H_ / 8, B_ * NSPLIT);
    reassembly_kernel<<<gsplit, 128>>>(x, out);
}